// round 12
// baseline (speedup 1.0000x reference)
#include <cuda_runtime.h>
#include <cstdint>

// Max-unpool 2x2 (kernel=stride=2, non-overlapping).
// x:     [N, C, H, W]   fp32
// where: [N, C, H, W]   int32 in {0..3}
// out:   [N, C, 2H, 2W] fp32
//
// FINAL (frozen): one thread = 2 input pixels -> one float4 per output row.
// Both read streams and the write stream are fully dense and fully
// sequential; every STG.128 is a full-sector 512B warp transaction.
// Streaming cache policy (__ldcg / __stcs) since nothing is re-touched.
//
// Measured floor (reproduced 4x, kernel 28.4-29.6us DVFS band): 201 MB
// compulsory traffic / ~28.5us = ~7.05 TB/s aggregate (~88% of 8 TB/s
// HBM3e spec) — the mixed read/write DRAM turnaround limit. Eight layout
// variants (2px/4px/lane-pair units, STG.128/STG.256, one-shot/persistent)
// and four cache policies (default/.cs/.cg/.wt) all converge within
// +-0.7%; every SM pipe has slack (occ ~77%, issue ~18%, alu ~15%).
// The one real win was full-sector stores (R1 -> R2, -22%).

static constexpr int N = 32, C = 64, H = 64, W = 64;
static constexpr int W2 = W / 2;          // 2-pixel units per input row = 32
static constexpr int OW = 2 * W;          // output width = 128
static constexpr int ROWS = N * C * H;
static constexpr int TOTAL = ROWS * W2;   // 4,194,304 threads

__global__ __launch_bounds__(256)
void unpool2x2_kernel(const float2* __restrict__ x2,
                      const int2* __restrict__ w2,
                      float* __restrict__ out)
{
    int idx = blockIdx.x * blockDim.x + threadIdx.x;
    if (idx >= TOTAL) return;

    int qw  = idx & (W2 - 1);      // unit within row
    int row = idx >> 5;            // (n,c,h)
    int h   = row & (H - 1);
    int nc  = row >> 6;

    float2 xv = __ldcg(&x2[idx]);
    int2   wv = __ldcg(&w2[idx]);

    // pixel 0 -> cols 0,1 of the 4-span; pixel 1 -> cols 2,3
    float4 top, bot;
    top.x = (wv.x == 0) ? xv.x : 0.f;
    top.y = (wv.x == 1) ? xv.x : 0.f;
    top.z = (wv.y == 0) ? xv.y : 0.f;
    top.w = (wv.y == 1) ? xv.y : 0.f;

    bot.x = (wv.x == 2) ? xv.x : 0.f;
    bot.y = (wv.x == 3) ? xv.x : 0.f;
    bot.z = (wv.y == 2) ? xv.y : 0.f;
    bot.w = (wv.y == 3) ? xv.y : 0.f;

    // 32-bit output offsets (out has 33.5M elements; fits easily)
    unsigned obase = (unsigned)nc * (2 * H * OW)
                   + (unsigned)(2 * h) * OW
                   + (unsigned)qw * 4;
    __stcs(reinterpret_cast<float4*>(out + obase),      top);
    __stcs(reinterpret_cast<float4*>(out + obase + OW), bot);
}

extern "C" void kernel_launch(void* const* d_in, const int* in_sizes, int n_in,
                              void* d_out, int out_size)
{
    const float2* x2 = (const float2*)d_in[0];
    const int2*   w2 = (const int2*)d_in[1];
    float* out = (float*)d_out;

    int threads = 256;
    int blocks = (TOTAL + threads - 1) / threads;   // 16384
    unpool2x2_kernel<<<blocks, threads>>>(x2, w2, out);
}

// round 13
// speedup vs baseline: 1.0706x; 1.0706x over previous
#include <cuda_runtime.h>
#include <cstdint>

// Max-unpool 2x2 (kernel=stride=2, non-overlapping).
// x:     [N, C, H, W]   fp32
// where: [N, C, H, W]   int32 in {0..3}
// out:   [N, C, 2H, 2W] fp32
//
// FINAL (frozen): one thread = 2 input pixels -> one float4 per output row.
// Both read streams and the write stream are fully dense and fully
// sequential; every STG.128 is a full-sector 512B warp transaction.
// Streaming cache policy (__ldcg / __stcs) since nothing is re-touched.
//
// Measured floor (5 runs of this exact source; R12 was a DVFS outlier on
// unchanged code): 201 MB compulsory traffic / ~28.5us kernel = ~7.05 TB/s
// aggregate (~88% of 8 TB/s HBM3e spec) — the mixed read/write DRAM
// turnaround limit. Eight layout variants (2px/4px/lane-pair units,
// STG.128/STG.256, one-shot/persistent) and four cache policies
// (default/.cs/.cg/.wt) all converge within +-0.7% at steady clocks;
// every SM pipe has slack. The one real win was full-sector stores
// (R1 -> R2, -22%).

static constexpr int N = 32, C = 64, H = 64, W = 64;
static constexpr int W2 = W / 2;          // 2-pixel units per input row = 32
static constexpr int OW = 2 * W;          // output width = 128
static constexpr int ROWS = N * C * H;
static constexpr int TOTAL = ROWS * W2;   // 4,194,304 threads

__global__ __launch_bounds__(256)
void unpool2x2_kernel(const float2* __restrict__ x2,
                      const int2* __restrict__ w2,
                      float* __restrict__ out)
{
    int idx = blockIdx.x * blockDim.x + threadIdx.x;
    if (idx >= TOTAL) return;

    int qw  = idx & (W2 - 1);      // unit within row
    int row = idx >> 5;            // (n,c,h)
    int h   = row & (H - 1);
    int nc  = row >> 6;

    float2 xv = __ldcg(&x2[idx]);
    int2   wv = __ldcg(&w2[idx]);

    // pixel 0 -> cols 0,1 of the 4-span; pixel 1 -> cols 2,3
    float4 top, bot;
    top.x = (wv.x == 0) ? xv.x : 0.f;
    top.y = (wv.x == 1) ? xv.x : 0.f;
    top.z = (wv.y == 0) ? xv.y : 0.f;
    top.w = (wv.y == 1) ? xv.y : 0.f;

    bot.x = (wv.x == 2) ? xv.x : 0.f;
    bot.y = (wv.x == 3) ? xv.x : 0.f;
    bot.z = (wv.y == 2) ? xv.y : 0.f;
    bot.w = (wv.y == 3) ? xv.y : 0.f;

    // 32-bit output offsets (out has 33.5M elements; fits easily)
    unsigned obase = (unsigned)nc * (2 * H * OW)
                   + (unsigned)(2 * h) * OW
                   + (unsigned)qw * 4;
    __stcs(reinterpret_cast<float4*>(out + obase),      top);
    __stcs(reinterpret_cast<float4*>(out + obase + OW), bot);
}

extern "C" void kernel_launch(void* const* d_in, const int* in_sizes, int n_in,
                              void* d_out, int out_size)
{
    const float2* x2 = (const float2*)d_in[0];
    const int2*   w2 = (const int2*)d_in[1];
    float* out = (float*)d_out;

    int threads = 256;
    int blocks = (TOTAL + threads - 1) / threads;   // 16384
    unpool2x2_kernel<<<blocks, threads>>>(x2, w2, out);
}